// round 15
// baseline (speedup 1.0000x reference)
#include <cuda_runtime.h>
#include <cuda_bf16.h>
#include <cuda_fp16.h>
#include <cstdint>

#define BB 8
#define NN 2048
#define FIN 256
#define FOUT 128
#define ALPHA 0.01f
#define TJ 32
#define NSPLIT 2
#define JHALF (NN / NSPLIT)          // 1024
#define NCHUNKH (JHALF / TJ)         // 32

// ---------------- scratch (allocation-free rule) ----------------
// __device__ globals are zero-init at module load; g_ms1/g_ms2 only receive
// monotone atomicMax of order-encoded floats -> graph replays deterministic.
__device__ uint16_t g_hh[(size_t)BB * NN * FOUT];          // fp16 of h
__device__ float g_s1[BB * NN];
__device__ float g_s2[BB * NN];
__device__ unsigned int g_ms1[BB];
__device__ unsigned int g_ms2[BB];
__device__ float g_pacc[(size_t)NSPLIT * BB * NN * FOUT];  // split-K partials, 16MB
__device__ float g_pd[NSPLIT * BB * NN];                   // partial denominators

// ---------------- helpers ----------------
__device__ __forceinline__ uint32_t smem_u32(const void* p) {
    uint32_t a;
    asm("{ .reg .u64 t; cvta.to.shared.u64 t, %1; cvt.u32.u64 %0, t; }"
        : "=r"(a) : "l"(p));
    return a;
}

__device__ __forceinline__ unsigned int f2o(float f) {
    unsigned int u = __float_as_uint(f);
    return (u & 0x80000000u) ? ~u : (u | 0x80000000u);
}
__device__ __forceinline__ float o2f(unsigned int v) {
    unsigned int u = (v & 0x80000000u) ? (v & 0x7fffffffu) : ~v;
    return __uint_as_float(u);
}

__device__ __forceinline__ void split2(float x, float y, uint32_t& hi, uint32_t& lo) {
    __nv_bfloat162 h = __float22bfloat162_rn(make_float2(x, y));
    float2 hf = __bfloat1622float2(h);
    __nv_bfloat162 l = __float22bfloat162_rn(make_float2(x - hf.x, y - hf.y));
    hi = *reinterpret_cast<uint32_t*>(&h);
    lo = *reinterpret_cast<uint32_t*>(&l);
}

__device__ __forceinline__ void mma16816(float* d, const uint32_t* a,
                                         uint32_t b0, uint32_t b1) {
    asm volatile(
        "mma.sync.aligned.m16n8k16.row.col.f32.bf16.bf16.f32 "
        "{%0,%1,%2,%3}, {%4,%5,%6,%7}, {%8,%9}, {%0,%1,%2,%3};"
        : "+f"(d[0]), "+f"(d[1]), "+f"(d[2]), "+f"(d[3])
        : "r"(a[0]), "r"(a[1]), "r"(a[2]), "r"(a[3]), "r"(b0), "r"(b1));
}

__device__ __forceinline__ void mma16816h(float* d, const uint32_t* a,
                                          uint32_t b0, uint32_t b1) {
    asm volatile(
        "mma.sync.aligned.m16n8k16.row.col.f32.f16.f16.f32 "
        "{%0,%1,%2,%3}, {%4,%5,%6,%7}, {%8,%9}, {%0,%1,%2,%3};"
        : "+f"(d[0]), "+f"(d[1]), "+f"(d[2]), "+f"(d[3])
        : "r"(a[0]), "r"(a[1]), "r"(a[2]), "r"(a[3]), "r"(b0), "r"(b1));
}

__device__ __forceinline__ void ldm_x4(uint32_t* r, uint32_t addr) {
    asm volatile("ldmatrix.sync.aligned.m8n8.x4.shared.b16 "
                 "{%0,%1,%2,%3}, [%4];"
                 : "=r"(r[0]), "=r"(r[1]), "=r"(r[2]), "=r"(r[3]) : "r"(addr));
}

__device__ __forceinline__ void ldm_x4_trans(uint32_t* r, uint32_t addr) {
    asm volatile("ldmatrix.sync.aligned.m8n8.x4.trans.shared.b16 "
                 "{%0,%1,%2,%3}, [%4];"
                 : "=r"(r[0]), "=r"(r[1]), "=r"(r[2]), "=r"(r[3]) : "r"(addr));
}

__device__ __forceinline__ uint32_t swz(uint32_t off) {
    return off ^ ((off >> 3) & 0x70);
}

__device__ __forceinline__ void cp16(uint32_t dst, const void* src) {
    asm volatile("cp.async.cg.shared.global [%0], [%1], 16;"
                 :: "r"(dst), "l"(src) : "memory");
}
#define CP_COMMIT() asm volatile("cp.async.commit_group;" ::: "memory")
#define CP_WAIT0()  asm volatile("cp.async.wait_group 0;" ::: "memory")
#define CP_WAIT1()  asm volatile("cp.async.wait_group 1;" ::: "memory")

// ======================= k_linear (unchanged from R14) ======================
#define L_INP0 0
#define L_W0   34816
#define L_INP1 68608
#define L_W1   103424
#define L_AHI  137216
#define L_ALO  153600
#define L_BHI  169984
#define L_BLO  186368
#define L_AS   202752
#define L_RED  203776
#define L_TOT  205824

__device__ __forceinline__ void lin_stage(uint32_t uBase, int set, int kc,
                                          const uint4* inp16, const uint4* w16,
                                          int tid) {
    const uint32_t iOff = set ? L_INP1 : L_INP0;
    const uint32_t wOff = set ? L_W1 : L_W0;
#pragma unroll
    for (int p = 0; p < 8; p++) {
        const int idx = tid + p * 256;
        const int row = idx >> 4, seg = idx & 15;
        cp16(uBase + iOff + (uint32_t)(row * 17 + seg) * 16,
             inp16 + (size_t)row * 64 + kc * 16 + seg);
    }
#pragma unroll
    for (int p = 0; p < 8; p++) {
        const int idx = tid + p * 256;
        const int k = idx >> 5, seg = idx & 31;
        cp16(uBase + wOff + (uint32_t)(k * 33 + seg) * 16,
             w16 + (size_t)(kc * 64 + k) * 32 + seg);
    }
}

__global__ __launch_bounds__(256, 1) void k_linear(const float* __restrict__ inp,
                                                   const float* __restrict__ W,
                                                   const float* __restrict__ a) {
    extern __shared__ char dsm[];
    const int tid  = threadIdx.x;
    const int lane = tid & 31;
    const int w    = tid >> 5;
    const int wi   = w & 3;
    const int wf   = w >> 2;
    const int g    = lane >> 2;
    const int q    = lane & 3;
    const int b    = blockIdx.y;
    const int i0   = blockIdx.x * 128;

    const uint32_t uBase = smem_u32(dsm);

    if (tid < 64)
        ((float4*)(dsm + L_AS))[tid] = ((const float4*)a)[tid];

    float acc[2][8][4];
#pragma unroll
    for (int mt = 0; mt < 2; mt++)
#pragma unroll
        for (int nt = 0; nt < 8; nt++)
#pragma unroll
            for (int c = 0; c < 4; c++) acc[mt][nt][c] = 0.f;

    const uint4* inp16 = (const uint4*)(inp + ((size_t)b * NN + i0) * FIN);
    const uint4* w16   = (const uint4*)W;

    const int lm_jrow = (((lane >> 3) & 1) * 8) + (lane & 7);
    const int lm_fcol = 64 * wf + ((lane >> 4) & 1) * 8;

    lin_stage(uBase, 0, 0, inp16, w16, tid);
    CP_COMMIT();

    for (int kc = 0; kc < 4; kc++) {
        if (kc + 1 < 4) {
            lin_stage(uBase, (kc + 1) & 1, kc + 1, inp16, w16, tid);
            CP_COMMIT();
            CP_WAIT1();
        } else {
            CP_WAIT0();
        }
        __syncthreads();

        {
            const uint32_t iOff = (kc & 1) ? L_INP1 : L_INP0;
            const int i = tid >> 1, kh = (tid & 1) * 32;
            const float* rp = (const float*)(dsm + iOff) + i * 68 + kh;
#pragma unroll
            for (int j = 0; j < 32; j += 4) {
                float4 v = *(const float4*)(rp + j);
                uint32_t h01, l01, h23, l23;
                split2(v.x, v.y, h01, l01);
                split2(v.z, v.w, h23, l23);
                const uint32_t off = swz((uint32_t)(i * 128 + (kh + j) * 2));
                *(uint2*)(dsm + L_AHI + off) = make_uint2(h01, h23);
                *(uint2*)(dsm + L_ALO + off) = make_uint2(l01, l23);
            }
        }
        {
            const uint32_t wOff = (kc & 1) ? L_W1 : L_W0;
            const int k = tid >> 2, fh = (tid & 3) * 32;
            const float* rp = (const float*)(dsm + wOff) + k * 132 + fh;
#pragma unroll
            for (int j = 0; j < 32; j += 4) {
                float4 v = *(const float4*)(rp + j);
                uint32_t h01, l01, h23, l23;
                split2(v.x, v.y, h01, l01);
                split2(v.z, v.w, h23, l23);
                const uint32_t off = swz((uint32_t)(k * 256 + (fh + j) * 2));
                *(uint2*)(dsm + L_BHI + off) = make_uint2(h01, h23);
                *(uint2*)(dsm + L_BLO + off) = make_uint2(l01, l23);
            }
        }
        __syncthreads();

#pragma unroll
        for (int ks = 0; ks < 4; ks++) {
            uint32_t Ah[2][4], Al[2][4];
#pragma unroll
            for (int mt = 0; mt < 2; mt++) {
                const uint32_t aoff = swz((uint32_t)(
                    (32 * wi + 16 * mt + (lane & 15)) * 128
                    + (ks * 16 + ((lane >> 4) & 1) * 8) * 2));
                ldm_x4(Ah[mt], uBase + L_AHI + aoff);
                ldm_x4(Al[mt], uBase + L_ALO + aoff);
            }
#pragma unroll
            for (int np = 0; np < 4; np++) {
                const uint32_t boff = swz((uint32_t)(
                    (ks * 16 + lm_jrow) * 256 + (lm_fcol + np * 16) * 2));
                uint32_t bh[4], bl[4];
                ldm_x4_trans(bh, uBase + L_BHI + boff);
                ldm_x4_trans(bl, uBase + L_BLO + boff);
#pragma unroll
                for (int mt = 0; mt < 2; mt++) {
                    mma16816(acc[mt][2 * np],     Ah[mt], bh[0], bh[1]);
                    mma16816(acc[mt][2 * np],     Ah[mt], bl[0], bl[1]);
                    mma16816(acc[mt][2 * np],     Al[mt], bh[0], bh[1]);
                    mma16816(acc[mt][2 * np + 1], Ah[mt], bh[2], bh[3]);
                    mma16816(acc[mt][2 * np + 1], Ah[mt], bl[2], bl[3]);
                    mma16816(acc[mt][2 * np + 1], Al[mt], bh[2], bh[3]);
                }
            }
        }
    }

    __syncthreads();
    float* red1 = (float*)(dsm + L_RED);
    float* red2 = red1 + 256;
    const float* aS = (const float*)(dsm + L_AS);

#pragma unroll
    for (int mt = 0; mt < 2; mt++) {
        float p1a = 0.f, p1b = 0.f, p2a = 0.f, p2b = 0.f;
        const int r0 = 32 * wi + 16 * mt + g;
        const size_t g0 = (size_t)b * NN + i0 + r0;
#pragma unroll
        for (int nt = 0; nt < 8; nt++) {
            const int col = 64 * wf + nt * 8 + 2 * q;
            const float a10 = aS[col], a11 = aS[col + 1];
            const float a20 = aS[128 + col], a21 = aS[128 + col + 1];
            const float v0 = acc[mt][nt][0], v1 = acc[mt][nt][1];
            const float v2 = acc[mt][nt][2], v3 = acc[mt][nt][3];
            p1a += v0 * a10 + v1 * a11;  p2a += v0 * a20 + v1 * a21;
            p1b += v2 * a10 + v3 * a11;  p2b += v2 * a20 + v3 * a21;
            __half2 h0 = __floats2half2_rn(v0, v1);
            __half2 h1 = __floats2half2_rn(v2, v3);
            *(uint32_t*)&g_hh[g0 * FOUT + col]       = *(uint32_t*)&h0;
            *(uint32_t*)&g_hh[(g0 + 8) * FOUT + col] = *(uint32_t*)&h1;
        }
        p1a += __shfl_down_sync(0xffffffffu, p1a, 2, 4);
        p1a += __shfl_down_sync(0xffffffffu, p1a, 1, 4);
        p1b += __shfl_down_sync(0xffffffffu, p1b, 2, 4);
        p1b += __shfl_down_sync(0xffffffffu, p1b, 1, 4);
        p2a += __shfl_down_sync(0xffffffffu, p2a, 2, 4);
        p2a += __shfl_down_sync(0xffffffffu, p2a, 1, 4);
        p2b += __shfl_down_sync(0xffffffffu, p2b, 2, 4);
        p2b += __shfl_down_sync(0xffffffffu, p2b, 1, 4);
        if (q == 0) {
            red1[r0 * 2 + wf] = p1a;  red1[(r0 + 8) * 2 + wf] = p1b;
            red2[r0 * 2 + wf] = p2a;  red2[(r0 + 8) * 2 + wf] = p2b;
        }
    }
    __syncthreads();
    if (tid < 128) {
        const size_t gid = (size_t)b * NN + i0 + tid;
        const float s1v = red1[tid * 2] + red1[tid * 2 + 1];
        const float s2v = red2[tid * 2] + red2[tid * 2 + 1];
        g_s1[gid] = s1v;
        g_s2[gid] = s2v;
        float m1 = s1v, m2 = s2v;
#pragma unroll
        for (int o = 16; o > 0; o >>= 1) {
            m1 = fmaxf(m1, __shfl_xor_sync(0xffffffffu, m1, o));
            m2 = fmaxf(m2, __shfl_xor_sync(0xffffffffu, m2, o));
        }
        if (lane == 0) {
            atomicMax(&g_ms1[b], f2o(m1));
            atomicMax(&g_ms2[b], f2o(m2));
        }
    }
}

// ======================= k_attn: 2-way split-K, fp16 1-term =================
// smem layout (bytes):
#define T_B   0          // 2 x 8192 (fp16 H)
#define T_A   16384      // 2 x 8192 (fp16 P)
#define T_S2  32768      // 4096 (this half's s2)
#define T_TOT 36864

__device__ __forceinline__ void stage_B(uint32_t uBase, int buf, int b,
                                        int j0, int tid) {
    const uint4* srcH = (const uint4*)(g_hh + ((size_t)b * NN + j0) * FOUT);
#pragma unroll
    for (int p = 0; p < 2; p++) {
        const int idx = tid + p * 256;
        const uint32_t ph = swz((uint32_t)idx * 16);
        cp16(uBase + T_B + buf * 8192 + ph, srcH + idx);
    }
}

__device__ __forceinline__ float p_comp(char* dsm, int buf, int j0c,
                                        int ip, int jq, float s1p, float C,
                                        int4 av0, int4 av1) {
    const float* s2c = (const float*)(dsm + T_S2) + j0c + jq;
    float4 s2a = *(const float4*)(s2c);
    float4 s2b = *(const float4*)(s2c + 4);
    float dsum = 0.f;
    const float s2v[8] = {s2a.x, s2a.y, s2a.z, s2a.w, s2b.x, s2b.y, s2b.z, s2b.w};
    const int   am[8]  = {av0.x, av0.y, av0.z, av0.w, av1.x, av1.y, av1.z, av1.w};
    float pv[8];
#pragma unroll
    for (int e = 0; e < 8; e++) {
        const float sc = s1p + s2v[e];
        const float le = fmaxf(sc, 0.f) + ALPHA * fminf(sc, 0.f);
        pv[e] = (am[e] > 0) ? __expf(le - C) : 0.f;
    }
#pragma unroll
    for (int e = 0; e < 8; e += 2) {
        __half2 hp = __floats2half2_rn(pv[e], pv[e + 1]);
        float2 pr = __half22float2(hp);
        dsum += pr.x + pr.y;
        const uint32_t off = swz((uint32_t)(ip * 128 + (jq + e) * 2));
        *(uint32_t*)(dsm + T_A + buf * 8192 + off) = *(uint32_t*)&hp;
    }
    return dsum;
}

__global__ __launch_bounds__(256, 3) void k_attn(const int* __restrict__ adj) {
    extern __shared__ char dsm[];
    const int tid  = threadIdx.x;
    const int lane = tid & 31;
    const int w    = tid >> 5;
    const int wi   = w & 1;
    const int wf   = w >> 1;
    const int b    = blockIdx.y;
    const int i0   = blockIdx.x * 64;
    const int z    = blockIdx.z;
    const int jb   = z * JHALF;

    const uint32_t uBase = smem_u32(dsm);

    const float mm = o2f(g_ms1[b]) + o2f(g_ms2[b]);
    const float C  = (mm > 0.f ? mm : ALPHA * mm) - 8.0f;

    const int ip = tid >> 2;
    const int jq = (tid & 3) * 8;
    const float s1p = g_s1[(size_t)b * NN + i0 + ip];
    const int* arow = adj + ((size_t)b * NN + i0 + ip) * NN + jb + jq;

    float acc[2][4][4];
#pragma unroll
    for (int mt = 0; mt < 2; mt++)
#pragma unroll
        for (int nt = 0; nt < 4; nt++)
#pragma unroll
            for (int c = 0; c < 4; c++) acc[mt][nt][c] = 0.f;

    const int lm_jrow = (((lane >> 3) & 1) * 8) + (lane & 7);
    const int lm_fcol = 32 * wf + ((lane >> 4) & 1) * 8;

    float dsum = 0.f;

    // ---- prologue: this half's s2 (4 KB), B(0), adj(0) in regs
    ((float4*)(dsm + T_S2))[tid] = ((const float4*)(g_s2 + (size_t)b * NN + jb))[tid];
    stage_B(uBase, 0, b, jb, tid);
    CP_COMMIT();
    int4 an0 = *(const int4*)(arow);
    int4 an1 = *(const int4*)(arow + 4);
    CP_WAIT0();
    __syncthreads();

    dsum += p_comp(dsm, 0, 0, ip, jq, s1p, C, an0, an1);
    __syncthreads();

    for (int ch = 0; ch < NCHUNKH; ch++) {
        int4 av0, av1;
        if (ch + 1 < NCHUNKH) {
            av0 = *(const int4*)(arow + (ch + 1) * TJ);
            av1 = *(const int4*)(arow + (ch + 1) * TJ + 4);
            stage_B(uBase, (ch + 1) & 1, b, jb + (ch + 1) * TJ, tid);
            CP_COMMIT();
        }

        const uint32_t buf8 = (uint32_t)(ch & 1) * 8192u;
#pragma unroll
        for (int ks = 0; ks < 2; ks++) {
            uint32_t Ah[2][4];
#pragma unroll
            for (int mt = 0; mt < 2; mt++) {
                const uint32_t aoff = swz((uint32_t)(
                    (32 * wi + 16 * mt + (lane & 15)) * 128
                    + (ks * 16 + ((lane >> 4) & 1) * 8) * 2));
                ldm_x4(Ah[mt], uBase + T_A + buf8 + aoff);
            }
#pragma unroll
            for (int np = 0; np < 2; np++) {
                const uint32_t boff = swz((uint32_t)(
                    (ks * 16 + lm_jrow) * 256 + (lm_fcol + np * 16) * 2));
                uint32_t bh[4];
                ldm_x4_trans(bh, uBase + T_B + buf8 + boff);
#pragma unroll
                for (int mt = 0; mt < 2; mt++) {
                    mma16816h(acc[mt][2 * np],     Ah[mt], bh[0], bh[1]);
                    mma16816h(acc[mt][2 * np + 1], Ah[mt], bh[2], bh[3]);
                }
            }
        }

        if (ch + 1 < NCHUNKH) {
            CP_WAIT0();
            dsum += p_comp(dsm, (ch + 1) & 1, (ch + 1) * TJ, ip, jq, s1p, C,
                           av0, av1);
        }
        __syncthreads();
    }

    // ---- partial denominator: quad reduce -> global
    dsum += __shfl_down_sync(0xffffffffu, dsum, 2, 4);
    dsum += __shfl_down_sync(0xffffffffu, dsum, 1, 4);
    if ((tid & 3) == 0)
        g_pd[(size_t)z * BB * NN + (size_t)b * NN + i0 + ip] = dsum;

    // ---- raw partial accumulators -> global
    {
        const int g2 = lane >> 2, q = lane & 3;
        float* pacc = g_pacc + (size_t)z * BB * NN * FOUT;
#pragma unroll
        for (int mt = 0; mt < 2; mt++) {
            const int r0 = 32 * wi + 16 * mt + g2;
            const size_t ga = ((size_t)b * NN + i0 + r0) * FOUT;
            const size_t gb2 = ((size_t)b * NN + i0 + r0 + 8) * FOUT;
#pragma unroll
            for (int nt = 0; nt < 4; nt++) {
                const int col = 32 * wf + nt * 8 + 2 * q;
                *(float2*)&pacc[ga + col]  = make_float2(acc[mt][nt][0], acc[mt][nt][1]);
                *(float2*)&pacc[gb2 + col] = make_float2(acc[mt][nt][2], acc[mt][nt][3]);
            }
        }
    }
}

// ======================= k_combine: out = relu((p0+p1)/(d0+d1)) =============
__global__ __launch_bounds__(256) void k_combine(float* __restrict__ out) {
    const size_t gid = (size_t)blockIdx.x * 256 + threadIdx.x;  // float4 index
    const float4 p0 = ((const float4*)g_pacc)[gid];
    const float4 p1 = ((const float4*)(g_pacc + (size_t)BB * NN * FOUT))[gid];
    const size_t row = gid >> 5;                 // 32 float4 per row
    const float dinv = 1.0f / (g_pd[row] + g_pd[(size_t)BB * NN + row]);
    float4 v;
    v.x = fmaxf((p0.x + p1.x) * dinv, 0.f);
    v.y = fmaxf((p0.y + p1.y) * dinv, 0.f);
    v.z = fmaxf((p0.z + p1.z) * dinv, 0.f);
    v.w = fmaxf((p0.w + p1.w) * dinv, 0.f);
    ((float4*)out)[gid] = v;
}

// ---------------------------------------------------------------------------
extern "C" void kernel_launch(void* const* d_in, const int* in_sizes, int n_in,
                              void* d_out, int out_size) {
    const float* inp = (const float*)d_in[0];   // (8, 2048, 256) f32
    const int*   adj = (const int*)d_in[1];     // (8, 2048, 2048) i32
    const float* W   = (const float*)d_in[2];   // (256, 128) f32
    const float* a   = (const float*)d_in[3];   // (256, 1) f32
    float* out = (float*)d_out;                 // (8, 2048, 128) f32

    cudaFuncSetAttribute(k_linear, cudaFuncAttributeMaxDynamicSharedMemorySize, L_TOT);
    cudaFuncSetAttribute(k_attn,   cudaFuncAttributeMaxDynamicSharedMemorySize, T_TOT);

    dim3 g1(NN / 128, BB);
    k_linear<<<g1, 256, L_TOT>>>(inp, W, a);

    dim3 g2(NN / 64, BB, NSPLIT);
    k_attn<<<g2, 256, T_TOT>>>(adj);

    k_combine<<<(BB * NN * FOUT / 4) / 256, 256>>>(out);
}

// round 16
// speedup vs baseline: 1.0745x; 1.0745x over previous
#include <cuda_runtime.h>
#include <cuda_bf16.h>
#include <cuda_fp16.h>
#include <cstdint>

#define BB 8
#define NN 2048
#define FIN 256
#define FOUT 128
#define ALPHA 0.01f
#define TJ 32
#define NCHUNK (NN / TJ)

// ---------------- scratch (allocation-free rule) ----------------
// __device__ globals are zero-init at module load; g_ms1/g_ms2 only receive
// monotone atomicMax of order-encoded floats -> graph replays deterministic.
__device__ uint16_t g_hh[(size_t)BB * NN * FOUT];    // fp16 of h
__device__ float g_s1[BB * NN];
__device__ float g_s2[BB * NN];
__device__ unsigned int g_ms1[BB];                   // order-encoded max(s1)
__device__ unsigned int g_ms2[BB];                   // order-encoded max(s2)

// ---------------- helpers ----------------
__device__ __forceinline__ uint32_t smem_u32(const void* p) {
    uint32_t a;
    asm("{ .reg .u64 t; cvta.to.shared.u64 t, %1; cvt.u32.u64 %0, t; }"
        : "=r"(a) : "l"(p));
    return a;
}

// order-preserving float<->uint for atomicMax (all real floats encode > 0u)
__device__ __forceinline__ unsigned int f2o(float f) {
    unsigned int u = __float_as_uint(f);
    return (u & 0x80000000u) ? ~u : (u | 0x80000000u);
}
__device__ __forceinline__ float o2f(unsigned int v) {
    unsigned int u = (v & 0x80000000u) ? (v & 0x7fffffffu) : ~v;
    return __uint_as_float(u);
}

// bf16 hi/lo split (k_linear internal tiles)
__device__ __forceinline__ void split2(float x, float y, uint32_t& hi, uint32_t& lo) {
    __nv_bfloat162 h = __float22bfloat162_rn(make_float2(x, y));
    float2 hf = __bfloat1622float2(h);
    __nv_bfloat162 l = __float22bfloat162_rn(make_float2(x - hf.x, y - hf.y));
    hi = *reinterpret_cast<uint32_t*>(&h);
    lo = *reinterpret_cast<uint32_t*>(&l);
}

__device__ __forceinline__ void mma16816(float* d, const uint32_t* a,
                                         uint32_t b0, uint32_t b1) {
    asm volatile(
        "mma.sync.aligned.m16n8k16.row.col.f32.bf16.bf16.f32 "
        "{%0,%1,%2,%3}, {%4,%5,%6,%7}, {%8,%9}, {%0,%1,%2,%3};"
        : "+f"(d[0]), "+f"(d[1]), "+f"(d[2]), "+f"(d[3])
        : "r"(a[0]), "r"(a[1]), "r"(a[2]), "r"(a[3]), "r"(b0), "r"(b1));
}

__device__ __forceinline__ void mma16816h(float* d, const uint32_t* a,
                                          uint32_t b0, uint32_t b1) {
    asm volatile(
        "mma.sync.aligned.m16n8k16.row.col.f32.f16.f16.f32 "
        "{%0,%1,%2,%3}, {%4,%5,%6,%7}, {%8,%9}, {%0,%1,%2,%3};"
        : "+f"(d[0]), "+f"(d[1]), "+f"(d[2]), "+f"(d[3])
        : "r"(a[0]), "r"(a[1]), "r"(a[2]), "r"(a[3]), "r"(b0), "r"(b1));
}

__device__ __forceinline__ void ldm_x4(uint32_t* r, uint32_t addr) {
    asm volatile("ldmatrix.sync.aligned.m8n8.x4.shared.b16 "
                 "{%0,%1,%2,%3}, [%4];"
                 : "=r"(r[0]), "=r"(r[1]), "=r"(r[2]), "=r"(r[3]) : "r"(addr));
}

__device__ __forceinline__ void ldm_x4_trans(uint32_t* r, uint32_t addr) {
    asm volatile("ldmatrix.sync.aligned.m8n8.x4.trans.shared.b16 "
                 "{%0,%1,%2,%3}, [%4];"
                 : "=r"(r[0]), "=r"(r[1]), "=r"(r[2]), "=r"(r[3]) : "r"(addr));
}

__device__ __forceinline__ uint32_t swz(uint32_t off) {
    return off ^ ((off >> 3) & 0x70);
}

__device__ __forceinline__ void cp16(uint32_t dst, const void* src) {
    asm volatile("cp.async.cg.shared.global [%0], [%1], 16;"
                 :: "r"(dst), "l"(src) : "memory");
}
#define CP_COMMIT() asm volatile("cp.async.commit_group;" ::: "memory")
#define CP_WAIT0()  asm volatile("cp.async.wait_group 0;" ::: "memory")
#define CP_WAIT1()  asm volatile("cp.async.wait_group 1;" ::: "memory")

// ======================= k_linear (unchanged from R14) ======================
#define L_INP0 0
#define L_W0   34816
#define L_INP1 68608
#define L_W1   103424
#define L_AHI  137216
#define L_ALO  153600
#define L_BHI  169984
#define L_BLO  186368
#define L_AS   202752
#define L_RED  203776
#define L_TOT  205824

__device__ __forceinline__ void lin_stage(uint32_t uBase, int set, int kc,
                                          const uint4* inp16, const uint4* w16,
                                          int tid) {
    const uint32_t iOff = set ? L_INP1 : L_INP0;
    const uint32_t wOff = set ? L_W1 : L_W0;
#pragma unroll
    for (int p = 0; p < 8; p++) {
        const int idx = tid + p * 256;
        const int row = idx >> 4, seg = idx & 15;
        cp16(uBase + iOff + (uint32_t)(row * 17 + seg) * 16,
             inp16 + (size_t)row * 64 + kc * 16 + seg);
    }
#pragma unroll
    for (int p = 0; p < 8; p++) {
        const int idx = tid + p * 256;
        const int k = idx >> 5, seg = idx & 31;
        cp16(uBase + wOff + (uint32_t)(k * 33 + seg) * 16,
             w16 + (size_t)(kc * 64 + k) * 32 + seg);
    }
}

__global__ __launch_bounds__(256, 1) void k_linear(const float* __restrict__ inp,
                                                   const float* __restrict__ W,
                                                   const float* __restrict__ a) {
    extern __shared__ char dsm[];
    const int tid  = threadIdx.x;
    const int lane = tid & 31;
    const int w    = tid >> 5;
    const int wi   = w & 3;
    const int wf   = w >> 2;
    const int g    = lane >> 2;
    const int q    = lane & 3;
    const int b    = blockIdx.y;
    const int i0   = blockIdx.x * 128;

    const uint32_t uBase = smem_u32(dsm);

    if (tid < 64)
        ((float4*)(dsm + L_AS))[tid] = ((const float4*)a)[tid];

    float acc[2][8][4];
#pragma unroll
    for (int mt = 0; mt < 2; mt++)
#pragma unroll
        for (int nt = 0; nt < 8; nt++)
#pragma unroll
            for (int c = 0; c < 4; c++) acc[mt][nt][c] = 0.f;

    const uint4* inp16 = (const uint4*)(inp + ((size_t)b * NN + i0) * FIN);
    const uint4* w16   = (const uint4*)W;

    const int lm_jrow = (((lane >> 3) & 1) * 8) + (lane & 7);
    const int lm_fcol = 64 * wf + ((lane >> 4) & 1) * 8;

    lin_stage(uBase, 0, 0, inp16, w16, tid);
    CP_COMMIT();

    for (int kc = 0; kc < 4; kc++) {
        if (kc + 1 < 4) {
            lin_stage(uBase, (kc + 1) & 1, kc + 1, inp16, w16, tid);
            CP_COMMIT();
            CP_WAIT1();
        } else {
            CP_WAIT0();
        }
        __syncthreads();

        {
            const uint32_t iOff = (kc & 1) ? L_INP1 : L_INP0;
            const int i = tid >> 1, kh = (tid & 1) * 32;
            const float* rp = (const float*)(dsm + iOff) + i * 68 + kh;
#pragma unroll
            for (int j = 0; j < 32; j += 4) {
                float4 v = *(const float4*)(rp + j);
                uint32_t h01, l01, h23, l23;
                split2(v.x, v.y, h01, l01);
                split2(v.z, v.w, h23, l23);
                const uint32_t off = swz((uint32_t)(i * 128 + (kh + j) * 2));
                *(uint2*)(dsm + L_AHI + off) = make_uint2(h01, h23);
                *(uint2*)(dsm + L_ALO + off) = make_uint2(l01, l23);
            }
        }
        {
            const uint32_t wOff = (kc & 1) ? L_W1 : L_W0;
            const int k = tid >> 2, fh = (tid & 3) * 32;
            const float* rp = (const float*)(dsm + wOff) + k * 132 + fh;
#pragma unroll
            for (int j = 0; j < 32; j += 4) {
                float4 v = *(const float4*)(rp + j);
                uint32_t h01, l01, h23, l23;
                split2(v.x, v.y, h01, l01);
                split2(v.z, v.w, h23, l23);
                const uint32_t off = swz((uint32_t)(k * 256 + (fh + j) * 2));
                *(uint2*)(dsm + L_BHI + off) = make_uint2(h01, h23);
                *(uint2*)(dsm + L_BLO + off) = make_uint2(l01, l23);
            }
        }
        __syncthreads();

#pragma unroll
        for (int ks = 0; ks < 4; ks++) {
            uint32_t Ah[2][4], Al[2][4];
#pragma unroll
            for (int mt = 0; mt < 2; mt++) {
                const uint32_t aoff = swz((uint32_t)(
                    (32 * wi + 16 * mt + (lane & 15)) * 128
                    + (ks * 16 + ((lane >> 4) & 1) * 8) * 2));
                ldm_x4(Ah[mt], uBase + L_AHI + aoff);
                ldm_x4(Al[mt], uBase + L_ALO + aoff);
            }
#pragma unroll
            for (int np = 0; np < 4; np++) {
                const uint32_t boff = swz((uint32_t)(
                    (ks * 16 + lm_jrow) * 256 + (lm_fcol + np * 16) * 2));
                uint32_t bh[4], bl[4];
                ldm_x4_trans(bh, uBase + L_BHI + boff);
                ldm_x4_trans(bl, uBase + L_BLO + boff);
#pragma unroll
                for (int mt = 0; mt < 2; mt++) {
                    mma16816(acc[mt][2 * np],     Ah[mt], bh[0], bh[1]);
                    mma16816(acc[mt][2 * np],     Ah[mt], bl[0], bl[1]);
                    mma16816(acc[mt][2 * np],     Al[mt], bh[0], bh[1]);
                    mma16816(acc[mt][2 * np + 1], Ah[mt], bh[2], bh[3]);
                    mma16816(acc[mt][2 * np + 1], Ah[mt], bl[2], bl[3]);
                    mma16816(acc[mt][2 * np + 1], Al[mt], bh[2], bh[3]);
                }
            }
        }
    }

    __syncthreads();
    float* red1 = (float*)(dsm + L_RED);
    float* red2 = red1 + 256;
    const float* aS = (const float*)(dsm + L_AS);

#pragma unroll
    for (int mt = 0; mt < 2; mt++) {
        float p1a = 0.f, p1b = 0.f, p2a = 0.f, p2b = 0.f;
        const int r0 = 32 * wi + 16 * mt + g;
        const size_t g0 = (size_t)b * NN + i0 + r0;
#pragma unroll
        for (int nt = 0; nt < 8; nt++) {
            const int col = 64 * wf + nt * 8 + 2 * q;
            const float a10 = aS[col], a11 = aS[col + 1];
            const float a20 = aS[128 + col], a21 = aS[128 + col + 1];
            const float v0 = acc[mt][nt][0], v1 = acc[mt][nt][1];
            const float v2 = acc[mt][nt][2], v3 = acc[mt][nt][3];
            p1a += v0 * a10 + v1 * a11;  p2a += v0 * a20 + v1 * a21;
            p1b += v2 * a10 + v3 * a11;  p2b += v2 * a20 + v3 * a21;
            __half2 h0 = __floats2half2_rn(v0, v1);
            __half2 h1 = __floats2half2_rn(v2, v3);
            *(uint32_t*)&g_hh[g0 * FOUT + col]       = *(uint32_t*)&h0;
            *(uint32_t*)&g_hh[(g0 + 8) * FOUT + col] = *(uint32_t*)&h1;
        }
        p1a += __shfl_down_sync(0xffffffffu, p1a, 2, 4);
        p1a += __shfl_down_sync(0xffffffffu, p1a, 1, 4);
        p1b += __shfl_down_sync(0xffffffffu, p1b, 2, 4);
        p1b += __shfl_down_sync(0xffffffffu, p1b, 1, 4);
        p2a += __shfl_down_sync(0xffffffffu, p2a, 2, 4);
        p2a += __shfl_down_sync(0xffffffffu, p2a, 1, 4);
        p2b += __shfl_down_sync(0xffffffffu, p2b, 2, 4);
        p2b += __shfl_down_sync(0xffffffffu, p2b, 1, 4);
        if (q == 0) {
            red1[r0 * 2 + wf] = p1a;  red1[(r0 + 8) * 2 + wf] = p1b;
            red2[r0 * 2 + wf] = p2a;  red2[(r0 + 8) * 2 + wf] = p2b;
        }
    }
    __syncthreads();
    if (tid < 128) {
        const size_t gid = (size_t)b * NN + i0 + tid;
        const float s1v = red1[tid * 2] + red1[tid * 2 + 1];
        const float s2v = red2[tid * 2] + red2[tid * 2 + 1];
        g_s1[gid] = s1v;
        g_s2[gid] = s2v;
        float m1 = s1v, m2 = s2v;
#pragma unroll
        for (int o = 16; o > 0; o >>= 1) {
            m1 = fmaxf(m1, __shfl_xor_sync(0xffffffffu, m1, o));
            m2 = fmaxf(m2, __shfl_xor_sync(0xffffffffu, m2, o));
        }
        if (lane == 0) {
            atomicMax(&g_ms1[b], f2o(m1));
            atomicMax(&g_ms2[b], f2o(m2));
        }
    }
}

// ======================= k_attn: fp16 1-term PV, occ-3 ======================
// smem layout (bytes):
#define T_B   0          // 2 x 8192 (fp16 H)
#define T_A   16384      // 2 x 8192 (fp16 P, 64 rows x 128B padded)
#define T_S2  32768      // 8192 (full batch s2, immutable)
#define T_DS  40960      // 256
#define T_TOT 41216

__device__ __forceinline__ void stage_B(uint32_t uBase, int buf, int b,
                                        int ch, int tid) {
    const int j0 = ch * TJ;
    const uint4* srcH = (const uint4*)(g_hh + ((size_t)b * NN + j0) * FOUT);
#pragma unroll
    for (int p = 0; p < 2; p++) {
        const int idx = tid + p * 256;               // 0..511 (8KB / 16B)
        const uint32_t ph = swz((uint32_t)idx * 16);
        cp16(uBase + T_B + buf * 8192 + ph, srcH + idx);
    }
}

// P = exp(leaky(s1+s2) - C) masked, fp16, written to A[buf].
// Returns partial row-sum of the ROUNDED fp16 values (num/denom consistent).
__device__ __forceinline__ float p_comp(char* dsm, int buf, int j0c,
                                        int ip, int jq, float s1p, float C,
                                        int4 av0, int4 av1) {
    const float* s2c = (const float*)(dsm + T_S2) + j0c + jq;
    float4 s2a = *(const float4*)(s2c);
    float4 s2b = *(const float4*)(s2c + 4);
    float dsum = 0.f;
    const float s2v[8] = {s2a.x, s2a.y, s2a.z, s2a.w, s2b.x, s2b.y, s2b.z, s2b.w};
    const int   am[8]  = {av0.x, av0.y, av0.z, av0.w, av1.x, av1.y, av1.z, av1.w};
    float pv[8];
#pragma unroll
    for (int e = 0; e < 8; e++) {
        const float sc = s1p + s2v[e];
        const float le = fmaxf(sc, 0.f) + ALPHA * fminf(sc, 0.f);
        pv[e] = (am[e] > 0) ? __expf(le - C) : 0.f;
    }
#pragma unroll
    for (int e = 0; e < 8; e += 2) {
        __half2 hp = __floats2half2_rn(pv[e], pv[e + 1]);
        float2 pr = __half22float2(hp);
        dsum += pr.x + pr.y;
        const uint32_t off = swz((uint32_t)(ip * 128 + (jq + e) * 2));
        *(uint32_t*)(dsm + T_A + buf * 8192 + off) = *(uint32_t*)&hp;
    }
    return dsum;
}

__global__ __launch_bounds__(256, 3) void k_attn(const int* __restrict__ adj,
                                                 float* __restrict__ out) {
    extern __shared__ char dsm[];
    const int tid  = threadIdx.x;
    const int lane = tid & 31;
    const int w    = tid >> 5;
    const int wi   = w & 1;    // 32-row strip (0..1)
    const int wf   = w >> 1;   // 32-col strip (0..3)
    const int b    = blockIdx.y;
    const int i0   = blockIdx.x * 64;

    const uint32_t uBase = smem_u32(dsm);

    // per-batch shift C = leaky(max s1 + max s2) - 8  (softmax-invariant)
    const float mm = o2f(g_ms1[b]) + o2f(g_ms2[b]);
    const float C  = (mm > 0.f ? mm : ALPHA * mm) - 8.0f;

    // P-phase mapping: 4 threads per row, 8 j's each
    const int ip = tid >> 2;          // 0..63
    const int jq = (tid & 3) * 8;
    const float s1p = g_s1[(size_t)b * NN + i0 + ip];
    const int* arow = adj + ((size_t)b * NN + i0 + ip) * NN + jq;

    float acc[2][4][4];
#pragma unroll
    for (int mt = 0; mt < 2; mt++)
#pragma unroll
        for (int nt = 0; nt < 4; nt++)
#pragma unroll
            for (int c = 0; c < 4; c++) acc[mt][nt][c] = 0.f;

    const int lm_jrow = (((lane >> 3) & 1) * 8) + (lane & 7);
    const int lm_fcol = 32 * wf + ((lane >> 4) & 1) * 8;

    float dsum = 0.f;

    // ---- prologue: s2 (8 KB, immutable), B(0), adj(0) in regs
    ((float4*)(dsm + T_S2))[tid]       = ((const float4*)(g_s2 + (size_t)b * NN))[tid];
    ((float4*)(dsm + T_S2))[tid + 256] = ((const float4*)(g_s2 + (size_t)b * NN))[tid + 256];
    stage_B(uBase, 0, b, 0, tid);
    CP_COMMIT();
    int4 an0 = *(const int4*)(arow);
    int4 an1 = *(const int4*)(arow + 4);
    CP_WAIT0();
    __syncthreads();                       // s2 + B(0) visible

    dsum += p_comp(dsm, 0, 0, ip, jq, s1p, C, an0, an1);   // P(0) -> A[0]
    __syncthreads();                       // A[0] visible

    for (int ch = 0; ch < NCHUNK; ch++) {
        // prefetch chunk ch+1: adj into registers, B via cp.async
        int4 av0, av1;
        if (ch + 1 < NCHUNK) {
            av0 = *(const int4*)(arow + (ch + 1) * TJ);
            av1 = *(const int4*)(arow + (ch + 1) * TJ + 4);
            stage_B(uBase, (ch + 1) & 1, b, ch + 1, tid);
            CP_COMMIT();
        }

        // MMA(ch): A[ch&1] (fp16 P), B[ch&1] (fp16 H) — single term
        const uint32_t buf8 = (uint32_t)(ch & 1) * 8192u;
#pragma unroll
        for (int ks = 0; ks < 2; ks++) {
            uint32_t Ah[2][4];
#pragma unroll
            for (int mt = 0; mt < 2; mt++) {
                const uint32_t aoff = swz((uint32_t)(
                    (32 * wi + 16 * mt + (lane & 15)) * 128
                    + (ks * 16 + ((lane >> 4) & 1) * 8) * 2));
                ldm_x4(Ah[mt], uBase + T_A + buf8 + aoff);
            }
#pragma unroll
            for (int np = 0; np < 2; np++) {
                const uint32_t boff = swz((uint32_t)(
                    (ks * 16 + lm_jrow) * 256 + (lm_fcol + np * 16) * 2));
                uint32_t bh[4];
                ldm_x4_trans(bh, uBase + T_B + buf8 + boff);
#pragma unroll
                for (int mt = 0; mt < 2; mt++) {
                    mma16816h(acc[mt][2 * np],     Ah[mt], bh[0], bh[1]);
                    mma16816h(acc[mt][2 * np + 1], Ah[mt], bh[2], bh[3]);
                }
            }
        }

        // P(ch+1): adj already in regs; wait only for B(ch+1) cp.async
        if (ch + 1 < NCHUNK) {
            CP_WAIT0();
            dsum += p_comp(dsm, (ch + 1) & 1, (ch + 1) * TJ, ip, jq, s1p, C,
                           av0, av1);
        }
        __syncthreads();   // A/B[(ch+1)&1] visible; buffers rotate
    }

    // ---- denominator reduce: 4 threads per row -> d_s[row]
    dsum += __shfl_down_sync(0xffffffffu, dsum, 2, 4);
    dsum += __shfl_down_sync(0xffffffffu, dsum, 1, 4);
    if ((tid & 3) == 0) ((float*)(dsm + T_DS))[ip] = dsum;
    __syncthreads();

    // ---- epilogue: out = relu(acc / d)
    const float* dS = (const float*)(dsm + T_DS);
    const int g2 = lane >> 2, q = lane & 3;
#pragma unroll
    for (int mt = 0; mt < 2; mt++) {
        const int r0 = 32 * wi + 16 * mt + g2;
        const float dinv0 = 1.0f / dS[r0];
        const float dinv1 = 1.0f / dS[r0 + 8];
        const size_t ga  = ((size_t)b * NN + i0 + r0) * FOUT;
        const size_t gb2 = ((size_t)b * NN + i0 + r0 + 8) * FOUT;
#pragma unroll
        for (int nt = 0; nt < 4; nt++) {
            const int col = 32 * wf + nt * 8 + 2 * q;
            float2 v0, v1;
            v0.x = fmaxf(acc[mt][nt][0] * dinv0, 0.f);
            v0.y = fmaxf(acc[mt][nt][1] * dinv0, 0.f);
            v1.x = fmaxf(acc[mt][nt][2] * dinv1, 0.f);
            v1.y = fmaxf(acc[mt][nt][3] * dinv1, 0.f);
            *(float2*)&out[ga + col]  = v0;
            *(float2*)&out[gb2 + col] = v1;
        }
    }
}

// ---------------------------------------------------------------------------
extern "C" void kernel_launch(void* const* d_in, const int* in_sizes, int n_in,
                              void* d_out, int out_size) {
    const float* inp = (const float*)d_in[0];   // (8, 2048, 256) f32
    const int*   adj = (const int*)d_in[1];     // (8, 2048, 2048) i32
    const float* W   = (const float*)d_in[2];   // (256, 128) f32
    const float* a   = (const float*)d_in[3];   // (256, 1) f32
    float* out = (float*)d_out;                 // (8, 2048, 128) f32

    cudaFuncSetAttribute(k_linear, cudaFuncAttributeMaxDynamicSharedMemorySize, L_TOT);
    cudaFuncSetAttribute(k_attn,   cudaFuncAttributeMaxDynamicSharedMemorySize, T_TOT);

    dim3 g1(NN / 128, BB);
    k_linear<<<g1, 256, L_TOT>>>(inp, W, a);

    dim3 g2(NN / 64, BB);
    k_attn<<<g2, 256, T_TOT>>>(adj, out);
}